// round 13
// baseline (speedup 1.0000x reference)
#include <cuda_runtime.h>
#include <cstdint>

#define N_NODES 16384
#define HDIM    64
#define MAXN    160          // max nnz/row: Binomial(16384,0.004)+1, mean 66, ~11 sigma headroom
#define NBLK    256          // gemm blocks (64 rows each)
#define BN_EPS  1e-5f

// ---------------- device scratch (no allocations allowed) ----------------
__device__ int   g_idx[N_NODES * MAXN];     // CSR-ish column indices per row
__device__ int   g_nnz[N_NODES];            // row degree (= row sum of adj)
__device__ __align__(16) float g_pooled[N_NODES * HDIM];
__device__ __align__(16) float g_t[N_NODES * HDIM];
__device__ __align__(16) float g_t2[N_NODES * HDIM];
__device__ __align__(16) float g_part[NBLK * 128];   // per-block [sum(64) | sumsq(64)]
__device__ __align__(16) float g_ab[128];            // BN affine: a[64], b[64]

// ---------------- K1: fused adj scan + layer-0 mean aggregation ----------------
// One warp per row; 8 coalesced LDG.128 per thread per iter (512B warp loads);
// measured at 80% of HBM spec (R10) — at the bandwidth floor.
__global__ __launch_bounds__(256) void scan_agg(const float* __restrict__ adj,
                                                const float* __restrict__ x,
                                                float* __restrict__ pooled) {
    int lane   = threadIdx.x & 31;
    int wlocal = threadIdx.x >> 5;
    int row    = (blockIdx.x << 3) + wlocal;        // 2048 blocks * 8 warps

    __shared__ int snnz[8];
    __shared__ int ids[8][MAXN];
    if (lane == 0) snnz[wlocal] = 0;
    __syncwarp();

    const uint4* base = reinterpret_cast<const uint4*>(adj + (size_t)row * N_NODES);
    int* rowidx = g_idx + (size_t)row * MAXN;

    for (int t = 0; t < 16; t++) {
        int ibase = t * 256;
        uint4 u[8];
        #pragma unroll
        for (int k = 0; k < 8; k++)
            u[k] = __ldcs(base + ibase + k * 32 + lane);

        unsigned any = 0;
        #pragma unroll
        for (int k = 0; k < 8; k++)
            any |= (u[k].x | u[k].y | u[k].z | u[k].w);

        if (any) {
            int loc[32];
            int cnt = 0;
            #pragma unroll
            for (int k = 0; k < 8; k++) {
                unsigned mk = u[k].x | u[k].y | u[k].z | u[k].w;
                if (mk) {
                    int col0 = (ibase + k * 32 + lane) * 4;
                    if (u[k].x) loc[cnt++] = col0;
                    if (u[k].y) loc[cnt++] = col0 + 1;
                    if (u[k].z) loc[cnt++] = col0 + 2;
                    if (u[k].w) loc[cnt++] = col0 + 3;
                }
            }
            int pos = atomicAdd(&snnz[wlocal], cnt);
            if (pos + cnt <= MAXN) {
                for (int i = 0; i < cnt; i++) {
                    ids[wlocal][pos + i] = loc[i];
                    rowidx[pos + i]      = loc[i];
                }
            }
        }
    }
    __syncwarp();
    int nnz = snnz[wlocal];
    if (lane == 0) g_nnz[row] = nnz;

    // phase 2: gather x over id list -> pooled[row,:]
    int half = lane >> 4;
    int cg   = lane & 15;
    float4 acc = make_float4(0.f, 0.f, 0.f, 0.f);

    int k = half;
    for (; k + 2 < nnz; k += 4) {
        int i0 = ids[wlocal][k];
        int i1 = ids[wlocal][k + 2];
        float4 v0 = *reinterpret_cast<const float4*>(x + (size_t)i0 * HDIM + cg * 4);
        float4 v1 = *reinterpret_cast<const float4*>(x + (size_t)i1 * HDIM + cg * 4);
        acc.x += v0.x + v1.x; acc.y += v0.y + v1.y;
        acc.z += v0.z + v1.z; acc.w += v0.w + v1.w;
    }
    if (k < nnz) {
        int i0 = ids[wlocal][k];
        float4 v0 = *reinterpret_cast<const float4*>(x + (size_t)i0 * HDIM + cg * 4);
        acc.x += v0.x; acc.y += v0.y; acc.z += v0.z; acc.w += v0.w;
    }
    acc.x += __shfl_down_sync(0xffffffffu, acc.x, 16);
    acc.y += __shfl_down_sync(0xffffffffu, acc.y, 16);
    acc.z += __shfl_down_sync(0xffffffffu, acc.z, 16);
    acc.w += __shfl_down_sync(0xffffffffu, acc.w, 16);
    if (half == 0) {
        float inv = 1.0f / (float)nnz;
        float4 r = make_float4(acc.x * inv, acc.y * inv, acc.z * inv, acc.w * inv);
        *reinterpret_cast<float4*>(pooled + (size_t)row * HDIM + cg * 4) = r;
    }
}

// ---------------- shared gemm core: Is[64][72] @ Ws[64x64] + bias -> out + BN partials ----------------
__device__ __forceinline__ void gemm_core(float (*Is)[72], const float* Ws,
                                          float (*redm)[64],
                                          const float* __restrict__ bias,
                                          float* __restrict__ out,
                                          float* __restrict__ part,
                                          int row0, int tid, int bid) {
    int ty = tid >> 4;              // row group: rows ty*4..ty*4+3
    int tx = tid & 15;              // col group: cols tx*4..tx*4+3

    float acc[4][4];
    float4 bv = *reinterpret_cast<const float4*>(bias + tx * 4);
    #pragma unroll
    for (int r = 0; r < 4; r++) {
        acc[r][0] = bv.x; acc[r][1] = bv.y; acc[r][2] = bv.z; acc[r][3] = bv.w;
    }

    #pragma unroll
    for (int k = 0; k < 64; k += 4) {
        float4 w0 = *reinterpret_cast<const float4*>(&Ws[(k + 0) * 64 + tx * 4]);
        float4 w1 = *reinterpret_cast<const float4*>(&Ws[(k + 1) * 64 + tx * 4]);
        float4 w2 = *reinterpret_cast<const float4*>(&Ws[(k + 2) * 64 + tx * 4]);
        float4 w3 = *reinterpret_cast<const float4*>(&Ws[(k + 3) * 64 + tx * 4]);
        #pragma unroll
        for (int r = 0; r < 4; r++) {
            float4 iv = *reinterpret_cast<const float4*>(&Is[ty * 4 + r][k]);
            acc[r][0] = fmaf(iv.x, w0.x, acc[r][0]);
            acc[r][1] = fmaf(iv.x, w0.y, acc[r][1]);
            acc[r][2] = fmaf(iv.x, w0.z, acc[r][2]);
            acc[r][3] = fmaf(iv.x, w0.w, acc[r][3]);
            acc[r][0] = fmaf(iv.y, w1.x, acc[r][0]);
            acc[r][1] = fmaf(iv.y, w1.y, acc[r][1]);
            acc[r][2] = fmaf(iv.y, w1.z, acc[r][2]);
            acc[r][3] = fmaf(iv.y, w1.w, acc[r][3]);
            acc[r][0] = fmaf(iv.z, w2.x, acc[r][0]);
            acc[r][1] = fmaf(iv.z, w2.y, acc[r][1]);
            acc[r][2] = fmaf(iv.z, w2.z, acc[r][2]);
            acc[r][3] = fmaf(iv.z, w2.w, acc[r][3]);
            acc[r][0] = fmaf(iv.w, w3.x, acc[r][0]);
            acc[r][1] = fmaf(iv.w, w3.y, acc[r][1]);
            acc[r][2] = fmaf(iv.w, w3.z, acc[r][2]);
            acc[r][3] = fmaf(iv.w, w3.w, acc[r][3]);
        }
    }

    #pragma unroll
    for (int r = 0; r < 4; r++) {
        float4 o = make_float4(acc[r][0], acc[r][1], acc[r][2], acc[r][3]);
        *reinterpret_cast<float4*>(out + (size_t)(row0 + ty * 4 + r) * HDIM + tx * 4) = o;
    }

    // per-block column stats: sum then sumsq
    float s[4];
    #pragma unroll
    for (int j = 0; j < 4; j++)
        s[j] = (acc[0][j] + acc[1][j]) + (acc[2][j] + acc[3][j]);
    #pragma unroll
    for (int j = 0; j < 4; j++) redm[ty][tx * 4 + j] = s[j];
    __syncthreads();
    if (tid < 64) {
        float v = 0.f;
        #pragma unroll
        for (int i = 0; i < 16; i++) v += redm[i][tid];
        part[(size_t)bid * 128 + tid] = v;
    }
    __syncthreads();
    #pragma unroll
    for (int j = 0; j < 4; j++) {
        float q = (acc[0][j] * acc[0][j] + acc[1][j] * acc[1][j]) +
                  (acc[2][j] * acc[2][j] + acc[3][j] * acc[3][j]);
        redm[ty][tx * 4 + j] = q;
    }
    __syncthreads();
    if (tid < 64) {
        float v = 0.f;
        #pragma unroll
        for (int i = 0; i < 16; i++) v += redm[i][tid];
        part[(size_t)bid * 128 + 64 + tid] = v;
    }
}

// ---------------- K3: register-blocked GEMM (R8 version, measured 8.9us) ----------------
// MODE==1 applies relu(a*x+b) (g_ab from bn_finalize) to the input tile.
template <int MODE>
__global__ __launch_bounds__(256) void gemm64(const float* __restrict__ in,
                                              const float* __restrict__ W,
                                              const float* __restrict__ bias,
                                              float* __restrict__ out,
                                              float* __restrict__ part) {
    __shared__ __align__(16) float Ws[64 * 64];
    __shared__ __align__(16) float Is[64][72];
    __shared__ float redm[16][64];

    int tid = threadIdx.x;
    const float4* W4 = reinterpret_cast<const float4*>(W);
    float4* Ws4 = reinterpret_cast<float4*>(Ws);
    #pragma unroll
    for (int i = tid; i < 1024; i += 256) Ws4[i] = W4[i];

    int row0 = (int)blockIdx.x * 64;
    const float4* in4 = reinterpret_cast<const float4*>(in + (size_t)row0 * HDIM);
    #pragma unroll
    for (int i = tid; i < 1024; i += 256) {
        int rr = i >> 4, cg = i & 15;
        float4 v = in4[i];
        if (MODE == 1) {
            float4 a4 = *reinterpret_cast<const float4*>(&g_ab[cg * 4]);
            float4 b4 = *reinterpret_cast<const float4*>(&g_ab[64 + cg * 4]);
            v.x = fmaxf(fmaf(a4.x, v.x, b4.x), 0.f);
            v.y = fmaxf(fmaf(a4.y, v.y, b4.y), 0.f);
            v.z = fmaxf(fmaf(a4.z, v.z, b4.z), 0.f);
            v.w = fmaxf(fmaf(a4.w, v.w, b4.w), 0.f);
        }
        *reinterpret_cast<float4*>(&Is[rr][cg * 4]) = v;
    }
    __syncthreads();

    gemm_core(Is, Ws, redm, bias, out, part, row0, tid, (int)blockIdx.x);
}

// ---------------- K3b: fused neighbor-mean(BN+ReLU(t2)) + GEMM ----------------
// Replaces agg<1> + gemm<0> for layer 1. Thread t gathers row rr = t>>2,
// column quarter cq = t&3 (16 cols): for each neighbor j of row rr, loads
// t2[j, cq*16..+15], applies relu(a*x+b) (g_ab), accumulates; writes mean
// into Is, then runs the shared gemm core. No cross-thread reduction needed.
__global__ __launch_bounds__(256) void gemm_agg(const float* __restrict__ t2src,
                                                const float* __restrict__ W,
                                                const float* __restrict__ bias,
                                                float* __restrict__ out,
                                                float* __restrict__ part) {
    __shared__ __align__(16) float Ws[64 * 64];
    __shared__ __align__(16) float Is[64][72];
    __shared__ float redm[16][64];

    int tid = threadIdx.x;
    const float4* W4 = reinterpret_cast<const float4*>(W);
    float4* Ws4 = reinterpret_cast<float4*>(Ws);
    #pragma unroll
    for (int i = tid; i < 1024; i += 256) Ws4[i] = W4[i];

    int row0 = (int)blockIdx.x * 64;
    int rr   = tid >> 2;                // 0..63: row within tile
    int cq   = tid & 3;                 // column quarter (16 cols)
    int row  = row0 + rr;
    int nnz  = g_nnz[row];
    const int* idp = g_idx + (size_t)row * MAXN;

    // BN coefficients for this thread's 16 columns
    float4 A[4], B[4];
    #pragma unroll
    for (int j = 0; j < 4; j++) {
        A[j] = *reinterpret_cast<const float4*>(&g_ab[cq * 16 + j * 4]);
        B[j] = *reinterpret_cast<const float4*>(&g_ab[64 + cq * 16 + j * 4]);
    }

    float4 acc[4];
    #pragma unroll
    for (int j = 0; j < 4; j++) acc[j] = make_float4(0.f, 0.f, 0.f, 0.f);

    int k = 0;
    for (; k + 2 <= nnz; k += 2) {      // 2 neighbors -> 8 float4 loads in flight
        int i0 = idp[k];
        int i1 = idp[k + 1];
        const float4* p0 = reinterpret_cast<const float4*>(t2src + (size_t)i0 * HDIM + cq * 16);
        const float4* p1 = reinterpret_cast<const float4*>(t2src + (size_t)i1 * HDIM + cq * 16);
        float4 v0[4], v1[4];
        #pragma unroll
        for (int j = 0; j < 4; j++) v0[j] = p0[j];
        #pragma unroll
        for (int j = 0; j < 4; j++) v1[j] = p1[j];
        #pragma unroll
        for (int j = 0; j < 4; j++) {
            acc[j].x += fmaxf(fmaf(A[j].x, v0[j].x, B[j].x), 0.f) +
                        fmaxf(fmaf(A[j].x, v1[j].x, B[j].x), 0.f);
            acc[j].y += fmaxf(fmaf(A[j].y, v0[j].y, B[j].y), 0.f) +
                        fmaxf(fmaf(A[j].y, v1[j].y, B[j].y), 0.f);
            acc[j].z += fmaxf(fmaf(A[j].z, v0[j].z, B[j].z), 0.f) +
                        fmaxf(fmaf(A[j].z, v1[j].z, B[j].z), 0.f);
            acc[j].w += fmaxf(fmaf(A[j].w, v0[j].w, B[j].w), 0.f) +
                        fmaxf(fmaf(A[j].w, v1[j].w, B[j].w), 0.f);
        }
    }
    if (k < nnz) {
        int i0 = idp[k];
        const float4* p0 = reinterpret_cast<const float4*>(t2src + (size_t)i0 * HDIM + cq * 16);
        #pragma unroll
        for (int j = 0; j < 4; j++) {
            float4 v = p0[j];
            acc[j].x += fmaxf(fmaf(A[j].x, v.x, B[j].x), 0.f);
            acc[j].y += fmaxf(fmaf(A[j].y, v.y, B[j].y), 0.f);
            acc[j].z += fmaxf(fmaf(A[j].z, v.z, B[j].z), 0.f);
            acc[j].w += fmaxf(fmaf(A[j].w, v.w, B[j].w), 0.f);
        }
    }

    float inv = 1.0f / (float)nnz;
    #pragma unroll
    for (int j = 0; j < 4; j++) {
        float4 r = make_float4(acc[j].x * inv, acc[j].y * inv,
                               acc[j].z * inv, acc[j].w * inv);
        *reinterpret_cast<float4*>(&Is[rr][cq * 16 + j * 4]) = r;
    }
    __syncthreads();

    gemm_core(Is, Ws, redm, bias, out, part, row0, tid, (int)blockIdx.x);
}

// ---------------- K4: reduce partials -> BN affine coefficients ----------------
__global__ __launch_bounds__(256) void bn_finalize(const float* __restrict__ g,
                                                   const float* __restrict__ be) {
    int c = blockIdx.x;                      // column 0..63
    int t = threadIdx.x;

    float s = 0.f, q = 0.f;
    #pragma unroll
    for (int b = t; b < NBLK; b += 256) {
        s += g_part[(size_t)b * 128 + c];
        q += g_part[(size_t)b * 128 + 64 + c];
    }
    __shared__ float ss[256];
    __shared__ float qq[256];
    ss[t] = s; qq[t] = q;
    __syncthreads();
    #pragma unroll
    for (int o = 128; o > 0; o >>= 1) {
        if (t < o) { ss[t] += ss[t + o]; qq[t] += qq[t + o]; }
        __syncthreads();
    }
    if (t == 0) {
        const float invn = 1.0f / (float)N_NODES;
        float mean = ss[0] * invn;
        float var  = qq[0] * invn - mean * mean;
        float a = g[c] * rsqrtf(var + BN_EPS);
        g_ab[c]      = a;
        g_ab[64 + c] = be[c] - mean * a;
    }
}

// ---------------- K5: elementwise h = relu(a*t2 + b) (final layer only) ----------------
__global__ __launch_bounds__(256) void apply_bn_relu(const float* __restrict__ t2,
                                                     float* __restrict__ h) {
    int i = blockIdx.x * 256 + threadIdx.x;
    int c = i & 63;
    h[i] = fmaxf(fmaf(g_ab[c], t2[i], g_ab[64 + c]), 0.f);
}

// ---------------- K6: pooled_h = graph_pool @ h  (general dense, zero-skip) ----------------
__global__ __launch_bounds__(256) void pool(const float* __restrict__ gp,
                                            const float* __restrict__ h,
                                            float* __restrict__ out) {
    int g = blockIdx.x;                 // 128 graphs
    int c    = threadIdx.x & 63;
    int lane = threadIdx.x >> 6;        // 4 node-lanes (warp-uniform)
    const float* gprow = gp + (size_t)g * N_NODES;

    float acc = 0.f;
    for (int n0 = lane; n0 < N_NODES; n0 += 32) {
        #pragma unroll
        for (int u = 0; u < 8; u++) {
            int n = n0 + u * 4;
            float w = __ldcs(gprow + n);
            if (w != 0.f) acc = fmaf(w, h[(size_t)n * HDIM + c], acc);
        }
    }
    __shared__ float red[4][64];
    red[lane][c] = acc;
    __syncthreads();
    if (threadIdx.x < 64)
        out[(size_t)g * HDIM + threadIdx.x] =
            (red[0][threadIdx.x] + red[1][threadIdx.x]) +
            (red[2][threadIdx.x] + red[3][threadIdx.x]);
}

// ---------------- launch ----------------
extern "C" void kernel_launch(void* const* d_in, const int* in_sizes, int n_in,
                              void* d_out, int out_size) {
    const float* x   = (const float*)d_in[0];
    const float* adj = (const float*)d_in[1];
    const float* gp  = (const float*)d_in[2];

    const float* P[16];
    for (int i = 0; i < 16; i++) P[i] = (const float*)d_in[3 + i];

    float* out      = (float*)d_out;
    float* h_nodes  = out + 128 * HDIM;   // [16384,64] after the [128,64] readout

    float *pooled, *t, *t2, *part;
    cudaGetSymbolAddress((void**)&pooled, g_pooled);
    cudaGetSymbolAddress((void**)&t,      g_t);
    cudaGetSymbolAddress((void**)&t2,     g_t2);
    cudaGetSymbolAddress((void**)&part,   g_part);

    // 1) fused: adj scan -> CSR + degrees + layer-0 aggregation (single launch)
    scan_agg<<<2048, 256>>>(adj, x, pooled);

    // ---- layer 0 MLP ----
    gemm64<0><<<NBLK, 256>>>(pooled, P[0], P[1], t, part);
    bn_finalize<<<64, 256>>>(P[2], P[3]);               // g1_0, be1_0
    gemm64<1><<<NBLK, 256>>>(t, P[4], P[5], t2, part);
    bn_finalize<<<64, 256>>>(P[6], P[7]);               // g_0, be_0 (for gemm_agg)

    // ---- layer 1: gather(BN+ReLU(t2)) fused directly into the first gemm ----
    gemm_agg<<<NBLK, 256>>>(t2, P[8], P[9], t, part);
    bn_finalize<<<64, 256>>>(P[10], P[11]);             // g1_1, be1_1
    gemm64<1><<<NBLK, 256>>>(t, P[12], P[13], t2, part);
    bn_finalize<<<64, 256>>>(P[14], P[15]);             // g_1, be_1
    apply_bn_relu<<<(N_NODES * HDIM) / 256, 256>>>(t2, h_nodes);

    // ---- graph readout ----
    pool<<<128, 256>>>(gp, h_nodes, out);

    (void)in_sizes; (void)n_in; (void)out_size;
}